// round 14
// baseline (speedup 1.0000x reference)
#include <cuda_runtime.h>
#include <cuda_bf16.h>
#include <cuda_fp16.h>
#include <cstdint>

// Problem shapes
#define BB 32
#define LL 48
#define DD 768
#define TT 32
#define VV 30522
#define HH 768
#define NPAD 30720   // 120 * 256
#define MPROJ 1056   // 32*33
#define MPROJP 1152
#define MTXT 1536

#define OUT_TEXT_ELEMS ((long)BB * LL * VV)
#define OUT_IOU_ELEMS  ((long)BB * 3 * TT * (TT+1))
#define OUT_IOU_BASE   (OUT_TEXT_ELEMS)
#define OUT_MASK_BASE  (OUT_TEXT_ELEMS + OUT_IOU_ELEMS)

// mega-kernel block ranges (all fp16 1-term, tile 128x256)
#define G1GRID 36    // gemm1: 12 rowtiles x 3 coltiles
#define PRGRID 81    // proj: 3 z x 9 rowtiles x 3 coltiles
#define VOGRID 1440  // vocab: 120 coltiles x 12 rowtiles (rowblk fastest)

// prep-kernel block ranges
#define SPGRID 7776    // elementwise fp32->fp16 of ht+hc
#define TW1GRID 1152   // w_t1 + w_i1 transpose: 4 z * (12 ktiles * 24 ntiles)
#define TW2GRID 11520  // w_t2 transpose: 12 ktiles * 960 ntiles

// Scratch (device globals; no allocations allowed)
__device__ int    g_ctr[16];   // [0..11]: per-row-block gemm1 tile count (target 3)
__device__ __half g_proj[3L * MPROJP * HH];
__device__ __half g_At16[(long)MTXT * DD];
__device__ __half g_Ac16[(long)MPROJ * DD];
__device__ __half g_H1hi[(long)MTXT * HH];
__device__ __half g_Bw1h[(long)HH * DD];
__device__ __half g_Bi1h[3L * HH * DD];
__device__ __half g_Bw2hi[(long)NPAD * DD];

// ---------------------------------------------------------------------------
// helpers
// ---------------------------------------------------------------------------
__device__ __forceinline__ uint32_t smem_u32(const void* p) {
    uint32_t a;
    asm("{ .reg .u64 t; cvta.to.shared.u64 t, %1; cvt.u32.u64 %0, t; }" : "=r"(a) : "l"(p));
    return a;
}
__device__ __forceinline__ void cp_async16(uint32_t saddr, const void* gptr) {
    asm volatile("cp.async.cg.shared.global [%0], [%1], 16;" :: "r"(saddr), "l"(gptr));
}
__device__ __forceinline__ void cp_async16z(uint32_t saddr, const void* gptr, bool pred) {
    int sz = pred ? 16 : 0;
    asm volatile("cp.async.cg.shared.global [%0], [%1], 16, %2;"
                 :: "r"(saddr), "l"(gptr), "r"(sz));
}
#define CP_COMMIT()  asm volatile("cp.async.commit_group;" ::: "memory")
#define CP_WAIT2()   asm volatile("cp.async.wait_group 2;" ::: "memory")
#define CP_WAIT1()   asm volatile("cp.async.wait_group 1;" ::: "memory")
#define CP_WAIT0()   asm volatile("cp.async.wait_group 0;" ::: "memory")

#define SWZ(o) ((o) ^ (((o) >> 3) & 0x70))

__device__ __forceinline__ void ldsm_x4(uint32_t addr, uint32_t& r0, uint32_t& r1,
                                        uint32_t& r2, uint32_t& r3) {
    asm volatile("ldmatrix.sync.aligned.m8n8.x4.shared.b16 {%0,%1,%2,%3}, [%4];"
                 : "=r"(r0), "=r"(r1), "=r"(r2), "=r"(r3) : "r"(addr));
}
__device__ __forceinline__ void mma_f16(float* d, const uint32_t* a, const uint32_t* b) {
    asm volatile(
        "mma.sync.aligned.m16n8k16.row.col.f32.f16.f16.f32 "
        "{%0,%1,%2,%3}, {%4,%5,%6,%7}, {%8,%9}, {%0,%1,%2,%3};"
        : "+f"(d[0]), "+f"(d[1]), "+f"(d[2]), "+f"(d[3])
        : "r"(a[0]), "r"(a[1]), "r"(a[2]), "r"(a[3]), "r"(b[0]), "r"(b[1]));
}

// producer/consumer sync
__device__ __forceinline__ void signal_ctr(int* c) {
    __syncthreads();
    if (threadIdx.x == 0) { __threadfence(); atomicAdd(c, 1); }
}
__device__ __forceinline__ void wait_ctr(int* c, int target) {
    if (threadIdx.x == 0) {
        volatile int* vc = c;
        while (*vc < target) __nanosleep(64);
    }
    __syncthreads();
    __threadfence();
}

// ---------------------------------------------------------------------------
// fp16 1-term mainloop: tile 128x256, K=768 (12 chunks of 64), 3-stage 48KB.
// 8 warps = 2(M) x 4(N), warp tile 64x64. Accumulates into acc[4][8][4].
// ---------------------------------------------------------------------------
#define KCHUNK 12

__device__ __forceinline__ void mainloop_f16(
    uint32_t sbase, int tid, int wid, int lane, int row0, int col0, int Mclip,
    const __half* __restrict__ A, const __half* __restrict__ B,
    float acc[4][8][4])
{
    const int wm = (wid & 1) * 64;
    const int wn = (wid >> 1) * 64;
    const int a_m  = lane & 15;
    const int a_kb = (lane >> 4) << 4;
    const int b_n  = (lane & 7) + ((lane >> 4) << 3);
    const int b_kb = ((lane >> 3) & 1) << 4;

#define LOAD_CHUNKF(KC)                                                         \
    {                                                                           \
        int kk = (KC) * 64;                                                     \
        uint32_t st = sbase + ((KC) % 3) * 49152;                               \
        _Pragma("unroll")                                                       \
        for (int i = 0; i < 4; i++) {                                           \
            int idx = tid + (i << 8);                                           \
            int m = idx >> 3, j = idx & 7;                                      \
            int grow = row0 + m;                                                \
            bool pa = grow < Mclip;                                             \
            cp_async16z(st + SWZ(m * 128 + j * 16),                             \
                        A + (size_t)(pa ? grow : 0) * DD + kk + j * 8, pa);     \
        }                                                                       \
        _Pragma("unroll")                                                       \
        for (int i = 0; i < 8; i++) {                                           \
            int idx = tid + (i << 8);                                           \
            int m = idx >> 3, j = idx & 7;                                      \
            cp_async16(st + 16384 + SWZ(m * 128 + j * 16),                      \
                       B + (size_t)(col0 + m) * DD + kk + j * 8);               \
        }                                                                       \
        CP_COMMIT();                                                            \
    }

    LOAD_CHUNKF(0);
    LOAD_CHUNKF(1);
    LOAD_CHUNKF(2);

    for (int kc = 0; kc < KCHUNK; kc++) {
        if (kc < KCHUNK - 2)       { CP_WAIT2(); }
        else if (kc == KCHUNK - 2) { CP_WAIT1(); }
        else                       { CP_WAIT0(); }
        __syncthreads();
        const uint32_t sA = sbase + (kc % 3) * 49152;
        const uint32_t sB = sA + 16384;

#pragma unroll
        for (int k16 = 0; k16 < 4; k16++) {
            const int kb = k16 * 32;
            uint32_t a[4][4], b[4][4];
#pragma unroll
            for (int mf = 0; mf < 4; mf++)
                ldsm_x4(sA + SWZ((wm + mf * 16 + a_m) * 128 + kb + a_kb),
                        a[mf][0], a[mf][1], a[mf][2], a[mf][3]);
#pragma unroll
            for (int np = 0; np < 4; np++)
                ldsm_x4(sB + SWZ((wn + np * 16 + b_n) * 128 + kb + b_kb),
                        b[np][0], b[np][1], b[np][2], b[np][3]);
#pragma unroll
            for (int mf = 0; mf < 4; mf++) {
#pragma unroll
                for (int nf = 0; nf < 8; nf++) {
                    uint32_t bb[2] = { b[nf >> 1][(nf & 1) * 2],
                                       b[nf >> 1][(nf & 1) * 2 + 1] };
                    mma_f16(acc[mf][nf], a[mf], bb);
                }
            }
        }
        __syncthreads();
        if (kc + 3 < KCHUNK) LOAD_CHUNKF(kc + 3);
    }
#undef LOAD_CHUNKF
}

// ---------------------------------------------------------------------------
// GEMM mega kernel: gemm1 (36) -> proj (81) -> vocab (1440).
// vocab: rowblk fastest (L2-resident B coltiles), waits g_ctr[rowblk] == 3.
// ---------------------------------------------------------------------------
__global__ __launch_bounds__(256) void mega_gemm(
    const __half* __restrict__ At16, const __half* __restrict__ Bw1h,
    const float* __restrict__ b_t1, __half* __restrict__ H1hi,
    const __half* __restrict__ Ac16, const __half* __restrict__ Bi1h,
    const float* __restrict__ b_i1, __half* __restrict__ proj,
    const __half* __restrict__ Bw2,
    const float* __restrict__ b_t2, float* __restrict__ out)
{
    extern __shared__ char smem[];
    const uint32_t sbase = smem_u32(smem);
    const int tid  = threadIdx.x;
    const int wid  = tid >> 5;
    const int lane = tid & 31;
    const int em = lane >> 2;
    const int en = (lane & 3) * 2;
    const int bid = blockIdx.x;
    const int wm = (wid & 1) * 64;
    const int wn = (wid >> 1) * 64;

    float acc[4][8][4];
#pragma unroll
    for (int i = 0; i < 4; i++)
#pragma unroll
        for (int j = 0; j < 8; j++)
#pragma unroll
            for (int r = 0; r < 4; r++) acc[i][j][r] = 0.f;

    if (bid < G1GRID) {
        // ===================== GEMM1: h1 -> fp16 =====================
        const int rowblk = bid / 3;
        const int row0 = rowblk * 128;
        const int col0 = (bid % 3) * 256;
        mainloop_f16(sbase, tid, wid, lane, row0, col0, MTXT, At16, Bw1h, acc);
#pragma unroll
        for (int mf = 0; mf < 4; mf++) {
#pragma unroll
            for (int half = 0; half < 2; half++) {
                int gr = row0 + wm + mf * 16 + em + half * 8;
#pragma unroll
                for (int nf = 0; nf < 8; nf++) {
                    int gc = col0 + wn + nf * 8 + en;
                    float vx = fmaxf(acc[mf][nf][half * 2]     + __ldg(b_t1 + gc), 0.f);
                    float vy = fmaxf(acc[mf][nf][half * 2 + 1] + __ldg(b_t1 + gc + 1), 0.f);
                    __half2 h;
                    h.x = __float2half_rn(vx);
                    h.y = __float2half_rn(vy);
                    *(__half2*)(H1hi + (size_t)gr * HH + gc) = h;
                }
            }
        }
        signal_ctr(&g_ctr[rowblk]);

    } else if (bid < G1GRID + PRGRID) {
        // ===================== projections (fp16 out) =====================
        const int p = bid - G1GRID;
        const int pz = p / 27;
        const int r  = p % 27;
        const int row0 = (r / 3) * 128;
        const int col0 = (r % 3) * 256;
        mainloop_f16(sbase, tid, wid, lane, row0, col0, MPROJ,
                     Ac16, Bi1h + (long)pz * HH * DD, acc);
        __half* Cf = proj + (long)pz * MPROJP * HH;
        const bool bias_on = (pz == 0);
#pragma unroll
        for (int mf = 0; mf < 4; mf++) {
#pragma unroll
            for (int half = 0; half < 2; half++) {
                int gr = row0 + wm + mf * 16 + em + half * 8;
#pragma unroll
                for (int nf = 0; nf < 8; nf++) {
                    int gc = col0 + wn + nf * 8 + en;
                    float vx = acc[mf][nf][half * 2];
                    float vy = acc[mf][nf][half * 2 + 1];
                    if (bias_on) { vx += __ldg(b_i1 + gc); vy += __ldg(b_i1 + gc + 1); }
                    __half2 h;
                    h.x = __float2half_rn(vx);
                    h.y = __float2half_rn(vy);
                    *(__half2*)(Cf + (size_t)gr * HH + gc) = h;
                }
            }
        }

    } else {
        // ===================== vocab GEMM (rowblk fastest) =====================
        const int v = bid - (G1GRID + PRGRID);
        const int rowblk = v % 12;
        const int col0 = (v / 12) * 256;
        const int row0 = rowblk * 128;
        wait_ctr(&g_ctr[rowblk], 3);
        mainloop_f16(sbase, tid, wid, lane, row0, col0, MTXT, H1hi, Bw2, acc);
#pragma unroll
        for (int mf = 0; mf < 4; mf++) {
#pragma unroll
            for (int half = 0; half < 2; half++) {
                int gr = row0 + wm + mf * 16 + em + half * 8;
                float* orow = out + (size_t)gr * VV;
#pragma unroll
                for (int nf = 0; nf < 8; nf++) {
                    int gc = col0 + wn + nf * 8 + en;
                    if (gc + 1 < VV) {
                        float2 vv = { acc[mf][nf][half * 2]     + __ldg(b_t2 + gc),
                                      acc[mf][nf][half * 2 + 1] + __ldg(b_t2 + gc + 1) };
                        __stcs((float2*)(orow + gc), vv);
                    } else if (gc < VV) {
                        orow[gc] = acc[mf][nf][half * 2] + __ldg(b_t2 + gc);
                    }
                }
            }
        }
    }
}

// ---------------------------------------------------------------------------
// Unified prep kernel (256 threads), coalesced transposes, all fp16
// ---------------------------------------------------------------------------
__global__ __launch_bounds__(256) void prep_k(
    const float* __restrict__ ht, const float* __restrict__ hc,
    __half* __restrict__ At16, __half* __restrict__ Ac16,
    const float* __restrict__ w_t1, const float* __restrict__ w_i1,
    __half* __restrict__ Bw1h, __half* __restrict__ Bi1h,
    const float* __restrict__ w_t2, __half* __restrict__ Bw2)
{
    const int bid = blockIdx.x;
    const int tid = threadIdx.x;

    if (bid < SPGRID) {
        if (bid == 0 && tid < 16) g_ctr[tid] = 0;
        long n1 = (long)MTXT * DD, n2 = (long)MPROJ * DD;
        long i = (long)bid * 256 + tid;
        if (i < n1) At16[i] = __float2half_rn(ht[i]);
        else if (i < n1 + n2) { i -= n1; Ac16[i] = __float2half_rn(hc[i]); }

    } else if (bid < SPGRID + TW1GRID) {
        const int bt = bid - SPGRID;
        const int z  = bt / 288;
        const int r  = bt % 288;
        const int k0 = (r / 24) * 64;
        const int n0 = (r % 24) * 32;
        const float* in; __half* hi;
        if (z == 0) { in = w_t1; hi = Bw1h; }
        else {
            in = w_i1 + (long)(z - 1) * DD * HH;
            hi = Bi1h + (long)(z - 1) * HH * DD;
        }
        __shared__ float t1[64][33];
        const int x = tid & 31, y0 = tid >> 5;
#pragma unroll
        for (int i = 0; i < 8; i++) {
            int y = y0 + i * 8;
            t1[y][x] = in[(long)(k0 + y) * HH + n0 + x];
        }
        __syncthreads();
        const int lane = tid & 31, wr = tid >> 5;
#pragma unroll
        for (int i = 0; i < 4; i++) {
            int n = wr + i * 8;
            __half2 h2;
            h2.x = __float2half_rn(t1[2 * lane][n]);
            h2.y = __float2half_rn(t1[2 * lane + 1][n]);
            *(__half2*)(hi + (long)(n0 + n) * DD + k0 + 2 * lane) = h2;
        }

    } else {
        const int bt = bid - (SPGRID + TW1GRID);
        const int k0 = (bt / 960) * 64;
        const int n0 = (bt % 960) * 32;
        __shared__ float t2[64][33];
        const int x = tid & 31, y0 = tid >> 5;
#pragma unroll
        for (int i = 0; i < 8; i++) {
            int y = y0 + i * 8;
            int n = n0 + x;
            t2[y][x] = (n < VV) ? w_t2[(long)(k0 + y) * VV + n] : 0.f;
        }
        __syncthreads();
        const int lane = tid & 31, wr = tid >> 5;
#pragma unroll
        for (int i = 0; i < 4; i++) {
            int n = wr + i * 8;
            __half2 h2;
            h2.x = __float2half_rn(t2[2 * lane][n]);
            h2.y = __float2half_rn(t2[2 * lane + 1][n]);
            *(__half2*)(Bw2 + (long)(n0 + n) * DD + k0 + 2 * lane) = h2;
        }
    }
}

// ---------------------------------------------------------------------------
// IoU combine + mask (fp16 proj reads, 192-thr blocks)
// ---------------------------------------------------------------------------
__global__ __launch_bounds__(192) void iou_mask_k(
    const __half* __restrict__ P, const float* __restrict__ w2,
    const float* __restrict__ b2, float* __restrict__ out)
{
    const int idx = blockIdx.x;
    const int e = idx % 33;
    const int s = (idx / 33) % 32;
    const int b = idx / (33 * 32);
    const int c = (s + e) >> 1;
    const int t = threadIdx.x;

    if (t == 100 && idx < 32 * 33) {
        int i = idx / 33, j = idx % 33;
        float v = 0.f;
        int hi = (i + 17 < 33) ? (i + 17) : 33;
        if (j >= i + 1 && j < hi) v = 1.f;
        if (i < 16 && (i & 1) == 0 && j >= 18 + i && ((j - 18 - i) & 1) == 0) v = 1.f;
        out[OUT_MASK_BASE + idx] = v;
    }

    const long CS = (long)MPROJP * HH;
    const __half2* ps = (const __half2*)(P + (long)(b * 33 + s) * HH) + 2 * t;
    const __half2* pc = (const __half2*)(P + CS + (long)(b * 33 + c) * HH) + 2 * t;
    const __half2* pe = (const __half2*)(P + 2 * CS + (long)(b * 33 + e) * HH) + 2 * t;
    const float4* wv = (const float4*)(w2) + t * 3;

    float2 a0 = __half22float2(ps[0]), a1 = __half22float2(ps[1]);
    float2 b0 = __half22float2(pc[0]), b1 = __half22float2(pc[1]);
    float2 c0 = __half22float2(pe[0]), c1 = __half22float2(pe[1]);
    float v0 = fmaxf(a0.x + b0.x + c0.x, 0.f);
    float v1 = fmaxf(a0.y + b0.y + c0.y, 0.f);
    float v2 = fmaxf(a1.x + b1.x + c1.x, 0.f);
    float v3 = fmaxf(a1.y + b1.y + c1.y, 0.f);
    float4 w0 = wv[0], w1 = wv[1], w2v = wv[2];
    float k0 = v0 * w0.x + v1 * w0.w + v2 * w1.z + v3 * w2v.y;
    float k1 = v0 * w0.y + v1 * w1.x + v2 * w1.w + v3 * w2v.z;
    float k2 = v0 * w0.z + v1 * w1.y + v2 * w2v.x + v3 * w2v.w;

#pragma unroll
    for (int off = 16; off; off >>= 1) {
        k0 += __shfl_xor_sync(0xFFFFFFFFu, k0, off);
        k1 += __shfl_xor_sync(0xFFFFFFFFu, k1, off);
        k2 += __shfl_xor_sync(0xFFFFFFFFu, k2, off);
    }
    __shared__ float red[3][6];
    const int lane = t & 31, w = t >> 5;
    if (lane == 0) { red[0][w] = k0; red[1][w] = k1; red[2][w] = k2; }
    __syncthreads();
    if (t == 0) {
        float r0 = __ldg(b2 + 0), r1 = __ldg(b2 + 1), r2 = __ldg(b2 + 2);
#pragma unroll
        for (int i = 0; i < 6; i++) { r0 += red[0][i]; r1 += red[1][i]; r2 += red[2][i]; }
        long base = OUT_IOU_BASE + ((long)b * 3) * (32 * 33) + (long)s * 33 + e;
        out[base + 0 * 32 * 33] = r0;
        out[base + 1 * 32 * 33] = r1;
        out[base + 2 * 32 * 33] = r2;
    }
}

// ---------------------------------------------------------------------------
extern "C" void kernel_launch(void* const* d_in, const int* in_sizes, int n_in,
                              void* d_out, int out_size)
{
    const float* ht   = (const float*)d_in[0];
    const float* hc   = (const float*)d_in[1];
    const float* w_t1 = (const float*)d_in[2];
    const float* b_t1 = (const float*)d_in[3];
    const float* w_t2 = (const float*)d_in[4];
    const float* b_t2 = (const float*)d_in[5];
    const float* w_i1 = (const float*)d_in[6];
    const float* b_i1 = (const float*)d_in[7];
    const float* w_i2 = (const float*)d_in[8];
    const float* b_i2 = (const float*)d_in[9];
    float* out = (float*)d_out;

    __half *proj, *At16, *Ac16, *H1hi, *Bw1h, *Bi1h, *Bw2hi;
    cudaGetSymbolAddress((void**)&proj, g_proj);
    cudaGetSymbolAddress((void**)&At16, g_At16);
    cudaGetSymbolAddress((void**)&Ac16, g_Ac16);
    cudaGetSymbolAddress((void**)&H1hi, g_H1hi);
    cudaGetSymbolAddress((void**)&Bw1h, g_Bw1h);
    cudaGetSymbolAddress((void**)&Bi1h, g_Bi1h);
    cudaGetSymbolAddress((void**)&Bw2hi, g_Bw2hi);

    cudaFuncSetAttribute(mega_gemm, cudaFuncAttributeMaxDynamicSharedMemorySize, 147456);

    // unified prep (all fp16)
    prep_k<<<SPGRID + TW1GRID + TW2GRID, 256>>>(
        ht, hc, At16, Ac16, w_t1, w_i1, Bw1h, Bi1h, w_t2, Bw2hi);
    // mega GEMM: gemm1 + projections + vocab (L2-friendly order + streaming stores)
    mega_gemm<<<G1GRID + PRGRID + VOGRID, 256, 147456>>>(
        At16, Bw1h, b_t1, H1hi,
        Ac16, Bi1h, b_i1, proj,
        Bw2hi, b_t2, out);
    // IoU combine + mask
    iou_mask_k<<<BB * TT * (TT + 1), 192>>>(proj, w_i2, b_i2, out);
}

// round 15
// speedup vs baseline: 1.0986x; 1.0986x over previous
#include <cuda_runtime.h>
#include <cuda_bf16.h>
#include <cuda_fp16.h>
#include <cstdint>

// Problem shapes
#define BB 32
#define LL 48
#define DD 768
#define TT 32
#define VV 30522
#define HH 768
#define NPAD 30720   // 120 * 256
#define MPROJ 1056   // 32*33
#define MPROJP 1152
#define MTXT 1536

#define OUT_TEXT_ELEMS ((long)BB * LL * VV)
#define OUT_IOU_ELEMS  ((long)BB * 3 * TT * (TT+1))
#define OUT_IOU_BASE   (OUT_TEXT_ELEMS)
#define OUT_MASK_BASE  (OUT_TEXT_ELEMS + OUT_IOU_ELEMS)

// mega-kernel block ranges (all fp16 1-term, tile 128x256)
#define G1GRID 36    // gemm1: 12 rowtiles x 3 coltiles
#define PRGRID 81    // proj: 3 z x 9 rowtiles x 3 coltiles
#define VOGRID 1440  // vocab: 12 rowtiles x 120 coltiles (coltile fastest)

// prep-kernel block ranges
#define SPGRID 7776    // elementwise fp32->fp16 of ht+hc
#define TW1GRID 1152   // w_t1 + w_i1 transpose: 4 z * (12 ktiles * 24 ntiles)
#define TW2GRID 11520  // w_t2 transpose: 12 ktiles * 960 ntiles

// Scratch (device globals; no allocations allowed)
__device__ int    g_ctr[16];   // [0..11]: per-row-block gemm1 tile count (target 3)
__device__ __half g_proj[3L * MPROJP * HH];
__device__ __half g_At16[(long)MTXT * DD];
__device__ __half g_Ac16[(long)MPROJ * DD];
__device__ __half g_H1hi[(long)MTXT * HH];
__device__ __half g_Bw1h[(long)HH * DD];
__device__ __half g_Bi1h[3L * HH * DD];
__device__ __half g_Bw2hi[(long)NPAD * DD];

// ---------------------------------------------------------------------------
// helpers
// ---------------------------------------------------------------------------
__device__ __forceinline__ uint32_t smem_u32(const void* p) {
    uint32_t a;
    asm("{ .reg .u64 t; cvta.to.shared.u64 t, %1; cvt.u32.u64 %0, t; }" : "=r"(a) : "l"(p));
    return a;
}
__device__ __forceinline__ void cp_async16(uint32_t saddr, const void* gptr) {
    asm volatile("cp.async.cg.shared.global [%0], [%1], 16;" :: "r"(saddr), "l"(gptr));
}
__device__ __forceinline__ void cp_async16z(uint32_t saddr, const void* gptr, bool pred) {
    int sz = pred ? 16 : 0;
    asm volatile("cp.async.cg.shared.global [%0], [%1], 16, %2;"
                 :: "r"(saddr), "l"(gptr), "r"(sz));
}
#define CP_COMMIT()  asm volatile("cp.async.commit_group;" ::: "memory")
#define CP_WAIT1()   asm volatile("cp.async.wait_group 1;" ::: "memory")
#define CP_WAIT0()   asm volatile("cp.async.wait_group 0;" ::: "memory")

#define SWZ(o) ((o) ^ (((o) >> 3) & 0x70))

__device__ __forceinline__ void ldsm_x4(uint32_t addr, uint32_t& r0, uint32_t& r1,
                                        uint32_t& r2, uint32_t& r3) {
    asm volatile("ldmatrix.sync.aligned.m8n8.x4.shared.b16 {%0,%1,%2,%3}, [%4];"
                 : "=r"(r0), "=r"(r1), "=r"(r2), "=r"(r3) : "r"(addr));
}
__device__ __forceinline__ void mma_f16(float* d, const uint32_t* a, const uint32_t* b) {
    asm volatile(
        "mma.sync.aligned.m16n8k16.row.col.f32.f16.f16.f32 "
        "{%0,%1,%2,%3}, {%4,%5,%6,%7}, {%8,%9}, {%0,%1,%2,%3};"
        : "+f"(d[0]), "+f"(d[1]), "+f"(d[2]), "+f"(d[3])
        : "r"(a[0]), "r"(a[1]), "r"(a[2]), "r"(a[3]), "r"(b[0]), "r"(b[1]));
}

// producer/consumer sync
__device__ __forceinline__ void signal_ctr(int* c) {
    __syncthreads();
    if (threadIdx.x == 0) { __threadfence(); atomicAdd(c, 1); }
}
__device__ __forceinline__ void wait_ctr(int* c, int target) {
    if (threadIdx.x == 0) {
        volatile int* vc = c;
        while (*vc < target) __nanosleep(64);
    }
    __syncthreads();
    __threadfence();
}

// ---------------------------------------------------------------------------
// fp16 1-term mainloop: tile 128x256, K=768 as 6 chunks of 128 (two 64-k
// halves per chunk), 2-stage double buffer, 96KB/stage (192KB total).
// Stage layout: [A0 16KB][A1 16KB][B0 32KB][B1 32KB].
// 8 warps = 2(M) x 4(N), warp tile 64x64. acc[4][8][4].
// ---------------------------------------------------------------------------
#define KCHUNK 6

__device__ __forceinline__ void mainloop_f16(
    uint32_t sbase, int tid, int wid, int lane, int row0, int col0, int Mclip,
    const __half* __restrict__ A, const __half* __restrict__ B,
    float acc[4][8][4])
{
    const int wm = (wid & 1) * 64;
    const int wn = (wid >> 1) * 64;
    const int a_m  = lane & 15;
    const int a_kb = (lane >> 4) << 4;
    const int b_n  = (lane & 7) + ((lane >> 4) << 3);
    const int b_kb = ((lane >> 3) & 1) << 4;

#define LOAD_CHUNKF(KC)                                                         \
    {                                                                           \
        int kk = (KC) * 128;                                                    \
        uint32_t st = sbase + ((KC) & 1) * 98304;                               \
        _Pragma("unroll")                                                       \
        for (int h = 0; h < 2; h++) {                                           \
            int kh = kk + h * 64;                                               \
            uint32_t sa = st + h * 16384;                                       \
            uint32_t sb = st + 32768 + h * 32768;                               \
            _Pragma("unroll")                                                   \
            for (int i = 0; i < 4; i++) {                                       \
                int idx = tid + (i << 8);                                       \
                int m = idx >> 3, j = idx & 7;                                  \
                int grow = row0 + m;                                            \
                bool pa = grow < Mclip;                                         \
                cp_async16z(sa + SWZ(m * 128 + j * 16),                         \
                            A + (size_t)(pa ? grow : 0) * DD + kh + j * 8, pa); \
            }                                                                   \
            _Pragma("unroll")                                                   \
            for (int i = 0; i < 8; i++) {                                       \
                int idx = tid + (i << 8);                                       \
                int m = idx >> 3, j = idx & 7;                                  \
                cp_async16(sb + SWZ(m * 128 + j * 16),                          \
                           B + (size_t)(col0 + m) * DD + kh + j * 8);           \
            }                                                                   \
        }                                                                       \
        CP_COMMIT();                                                            \
    }

    LOAD_CHUNKF(0);
    LOAD_CHUNKF(1);

    for (int kc = 0; kc < KCHUNK; kc++) {
        if (kc < KCHUNK - 1) { CP_WAIT1(); } else { CP_WAIT0(); }
        __syncthreads();
        const uint32_t st = sbase + (kc & 1) * 98304;

#pragma unroll
        for (int k16 = 0; k16 < 8; k16++) {
            const int hh = k16 >> 2;
            const int kb = (k16 & 3) * 32;
            const uint32_t sA = st + hh * 16384;
            const uint32_t sB = st + 32768 + hh * 32768;
            uint32_t a[4][4], b[4][4];
#pragma unroll
            for (int mf = 0; mf < 4; mf++)
                ldsm_x4(sA + SWZ((wm + mf * 16 + a_m) * 128 + kb + a_kb),
                        a[mf][0], a[mf][1], a[mf][2], a[mf][3]);
#pragma unroll
            for (int np = 0; np < 4; np++)
                ldsm_x4(sB + SWZ((wn + np * 16 + b_n) * 128 + kb + b_kb),
                        b[np][0], b[np][1], b[np][2], b[np][3]);
#pragma unroll
            for (int mf = 0; mf < 4; mf++) {
#pragma unroll
                for (int nf = 0; nf < 8; nf++) {
                    uint32_t bb[2] = { b[nf >> 1][(nf & 1) * 2],
                                       b[nf >> 1][(nf & 1) * 2 + 1] };
                    mma_f16(acc[mf][nf], a[mf], bb);
                }
            }
        }
        __syncthreads();
        if (kc + 2 < KCHUNK) LOAD_CHUNKF(kc + 2);
    }
#undef LOAD_CHUNKF
}

// ---------------------------------------------------------------------------
// GEMM mega kernel: gemm1 (36) -> proj (81) -> vocab (1440).
// vocab: coltile fastest (R13 order), waits g_ctr[rowblk] == 3.
// ---------------------------------------------------------------------------
__global__ __launch_bounds__(256) void mega_gemm(
    const __half* __restrict__ At16, const __half* __restrict__ Bw1h,
    const float* __restrict__ b_t1, __half* __restrict__ H1hi,
    const __half* __restrict__ Ac16, const __half* __restrict__ Bi1h,
    const float* __restrict__ b_i1, __half* __restrict__ proj,
    const __half* __restrict__ Bw2,
    const float* __restrict__ b_t2, float* __restrict__ out)
{
    extern __shared__ char smem[];
    const uint32_t sbase = smem_u32(smem);
    const int tid  = threadIdx.x;
    const int wid  = tid >> 5;
    const int lane = tid & 31;
    const int em = lane >> 2;
    const int en = (lane & 3) * 2;
    const int bid = blockIdx.x;
    const int wm = (wid & 1) * 64;
    const int wn = (wid >> 1) * 64;

    float acc[4][8][4];
#pragma unroll
    for (int i = 0; i < 4; i++)
#pragma unroll
        for (int j = 0; j < 8; j++)
#pragma unroll
            for (int r = 0; r < 4; r++) acc[i][j][r] = 0.f;

    if (bid < G1GRID) {
        // ===================== GEMM1: h1 -> fp16 =====================
        const int rowblk = bid / 3;
        const int row0 = rowblk * 128;
        const int col0 = (bid % 3) * 256;
        mainloop_f16(sbase, tid, wid, lane, row0, col0, MTXT, At16, Bw1h, acc);
#pragma unroll
        for (int mf = 0; mf < 4; mf++) {
#pragma unroll
            for (int half = 0; half < 2; half++) {
                int gr = row0 + wm + mf * 16 + em + half * 8;
#pragma unroll
                for (int nf = 0; nf < 8; nf++) {
                    int gc = col0 + wn + nf * 8 + en;
                    float vx = fmaxf(acc[mf][nf][half * 2]     + __ldg(b_t1 + gc), 0.f);
                    float vy = fmaxf(acc[mf][nf][half * 2 + 1] + __ldg(b_t1 + gc + 1), 0.f);
                    __half2 h;
                    h.x = __float2half_rn(vx);
                    h.y = __float2half_rn(vy);
                    *(__half2*)(H1hi + (size_t)gr * HH + gc) = h;
                }
            }
        }
        signal_ctr(&g_ctr[rowblk]);

    } else if (bid < G1GRID + PRGRID) {
        // ===================== projections (fp16 out) =====================
        const int p = bid - G1GRID;
        const int pz = p / 27;
        const int r  = p % 27;
        const int row0 = (r / 3) * 128;
        const int col0 = (r % 3) * 256;
        mainloop_f16(sbase, tid, wid, lane, row0, col0, MPROJ,
                     Ac16, Bi1h + (long)pz * HH * DD, acc);
        __half* Cf = proj + (long)pz * MPROJP * HH;
        const bool bias_on = (pz == 0);
#pragma unroll
        for (int mf = 0; mf < 4; mf++) {
#pragma unroll
            for (int half = 0; half < 2; half++) {
                int gr = row0 + wm + mf * 16 + em + half * 8;
#pragma unroll
                for (int nf = 0; nf < 8; nf++) {
                    int gc = col0 + wn + nf * 8 + en;
                    float vx = acc[mf][nf][half * 2];
                    float vy = acc[mf][nf][half * 2 + 1];
                    if (bias_on) { vx += __ldg(b_i1 + gc); vy += __ldg(b_i1 + gc + 1); }
                    __half2 h;
                    h.x = __float2half_rn(vx);
                    h.y = __float2half_rn(vy);
                    *(__half2*)(Cf + (size_t)gr * HH + gc) = h;
                }
            }
        }

    } else {
        // ===================== vocab GEMM (coltile fastest) =====================
        const int v = bid - (G1GRID + PRGRID);
        const int col0 = (v % 120) * 256;
        const int rowblk = v / 120;
        const int row0 = rowblk * 128;
        wait_ctr(&g_ctr[rowblk], 3);
        mainloop_f16(sbase, tid, wid, lane, row0, col0, MTXT, H1hi, Bw2, acc);
#pragma unroll
        for (int mf = 0; mf < 4; mf++) {
#pragma unroll
            for (int half = 0; half < 2; half++) {
                int gr = row0 + wm + mf * 16 + em + half * 8;
                float* orow = out + (size_t)gr * VV;
#pragma unroll
                for (int nf = 0; nf < 8; nf++) {
                    int gc = col0 + wn + nf * 8 + en;
                    if (gc + 1 < VV) {
                        float2 vv = { acc[mf][nf][half * 2]     + __ldg(b_t2 + gc),
                                      acc[mf][nf][half * 2 + 1] + __ldg(b_t2 + gc + 1) };
                        *(float2*)(orow + gc) = vv;
                    } else if (gc < VV) {
                        orow[gc] = acc[mf][nf][half * 2] + __ldg(b_t2 + gc);
                    }
                }
            }
        }
    }
}

// ---------------------------------------------------------------------------
// Unified prep kernel (256 threads), coalesced transposes, all fp16
// ---------------------------------------------------------------------------
__global__ __launch_bounds__(256) void prep_k(
    const float* __restrict__ ht, const float* __restrict__ hc,
    __half* __restrict__ At16, __half* __restrict__ Ac16,
    const float* __restrict__ w_t1, const float* __restrict__ w_i1,
    __half* __restrict__ Bw1h, __half* __restrict__ Bi1h,
    const float* __restrict__ w_t2, __half* __restrict__ Bw2)
{
    const int bid = blockIdx.x;
    const int tid = threadIdx.x;

    if (bid < SPGRID) {
        if (bid == 0 && tid < 16) g_ctr[tid] = 0;
        long n1 = (long)MTXT * DD, n2 = (long)MPROJ * DD;
        long i = (long)bid * 256 + tid;
        if (i < n1) At16[i] = __float2half_rn(ht[i]);
        else if (i < n1 + n2) { i -= n1; Ac16[i] = __float2half_rn(hc[i]); }

    } else if (bid < SPGRID + TW1GRID) {
        const int bt = bid - SPGRID;
        const int z  = bt / 288;
        const int r  = bt % 288;
        const int k0 = (r / 24) * 64;
        const int n0 = (r % 24) * 32;
        const float* in; __half* hi;
        if (z == 0) { in = w_t1; hi = Bw1h; }
        else {
            in = w_i1 + (long)(z - 1) * DD * HH;
            hi = Bi1h + (long)(z - 1) * HH * DD;
        }
        __shared__ float t1[64][33];
        const int x = tid & 31, y0 = tid >> 5;
#pragma unroll
        for (int i = 0; i < 8; i++) {
            int y = y0 + i * 8;
            t1[y][x] = in[(long)(k0 + y) * HH + n0 + x];
        }
        __syncthreads();
        const int lane = tid & 31, wr = tid >> 5;
#pragma unroll
        for (int i = 0; i < 4; i++) {
            int n = wr + i * 8;
            __half2 h2;
            h2.x = __float2half_rn(t1[2 * lane][n]);
            h2.y = __float2half_rn(t1[2 * lane + 1][n]);
            *(__half2*)(hi + (long)(n0 + n) * DD + k0 + 2 * lane) = h2;
        }

    } else {
        const int bt = bid - (SPGRID + TW1GRID);
        const int k0 = (bt / 960) * 64;
        const int n0 = (bt % 960) * 32;
        __shared__ float t2[64][33];
        const int x = tid & 31, y0 = tid >> 5;
#pragma unroll
        for (int i = 0; i < 8; i++) {
            int y = y0 + i * 8;
            int n = n0 + x;
            t2[y][x] = (n < VV) ? w_t2[(long)(k0 + y) * VV + n] : 0.f;
        }
        __syncthreads();
        const int lane = tid & 31, wr = tid >> 5;
#pragma unroll
        for (int i = 0; i < 4; i++) {
            int n = wr + i * 8;
            __half2 h2;
            h2.x = __float2half_rn(t2[2 * lane][n]);
            h2.y = __float2half_rn(t2[2 * lane + 1][n]);
            *(__half2*)(Bw2 + (long)(n0 + n) * DD + k0 + 2 * lane) = h2;
        }
    }
}

// ---------------------------------------------------------------------------
// IoU combine + mask (fp16 proj reads, 192-thr blocks)
// ---------------------------------------------------------------------------
__global__ __launch_bounds__(192) void iou_mask_k(
    const __half* __restrict__ P, const float* __restrict__ w2,
    const float* __restrict__ b2, float* __restrict__ out)
{
    const int idx = blockIdx.x;
    const int e = idx % 33;
    const int s = (idx / 33) % 32;
    const int b = idx / (33 * 32);
    const int c = (s + e) >> 1;
    const int t = threadIdx.x;

    if (t == 100 && idx < 32 * 33) {
        int i = idx / 33, j = idx % 33;
        float v = 0.f;
        int hi = (i + 17 < 33) ? (i + 17) : 33;
        if (j >= i + 1 && j < hi) v = 1.f;
        if (i < 16 && (i & 1) == 0 && j >= 18 + i && ((j - 18 - i) & 1) == 0) v = 1.f;
        out[OUT_MASK_BASE + idx] = v;
    }

    const long CS = (long)MPROJP * HH;
    const __half2* ps = (const __half2*)(P + (long)(b * 33 + s) * HH) + 2 * t;
    const __half2* pc = (const __half2*)(P + CS + (long)(b * 33 + c) * HH) + 2 * t;
    const __half2* pe = (const __half2*)(P + 2 * CS + (long)(b * 33 + e) * HH) + 2 * t;
    const float4* wv = (const float4*)(w2) + t * 3;

    float2 a0 = __half22float2(ps[0]), a1 = __half22float2(ps[1]);
    float2 b0 = __half22float2(pc[0]), b1 = __half22float2(pc[1]);
    float2 c0 = __half22float2(pe[0]), c1 = __half22float2(pe[1]);
    float v0 = fmaxf(a0.x + b0.x + c0.x, 0.f);
    float v1 = fmaxf(a0.y + b0.y + c0.y, 0.f);
    float v2 = fmaxf(a1.x + b1.x + c1.x, 0.f);
    float v3 = fmaxf(a1.y + b1.y + c1.y, 0.f);
    float4 w0 = wv[0], w1 = wv[1], w2v = wv[2];
    float k0 = v0 * w0.x + v1 * w0.w + v2 * w1.z + v3 * w2v.y;
    float k1 = v0 * w0.y + v1 * w1.x + v2 * w1.w + v3 * w2v.z;
    float k2 = v0 * w0.z + v1 * w1.y + v2 * w2v.x + v3 * w2v.w;

#pragma unroll
    for (int off = 16; off; off >>= 1) {
        k0 += __shfl_xor_sync(0xFFFFFFFFu, k0, off);
        k1 += __shfl_xor_sync(0xFFFFFFFFu, k1, off);
        k2 += __shfl_xor_sync(0xFFFFFFFFu, k2, off);
    }
    __shared__ float red[3][6];
    const int lane = t & 31, w = t >> 5;
    if (lane == 0) { red[0][w] = k0; red[1][w] = k1; red[2][w] = k2; }
    __syncthreads();
    if (t == 0) {
        float r0 = __ldg(b2 + 0), r1 = __ldg(b2 + 1), r2 = __ldg(b2 + 2);
#pragma unroll
        for (int i = 0; i < 6; i++) { r0 += red[0][i]; r1 += red[1][i]; r2 += red[2][i]; }
        long base = OUT_IOU_BASE + ((long)b * 3) * (32 * 33) + (long)s * 33 + e;
        out[base + 0 * 32 * 33] = r0;
        out[base + 1 * 32 * 33] = r1;
        out[base + 2 * 32 * 33] = r2;
    }
}

// ---------------------------------------------------------------------------
extern "C" void kernel_launch(void* const* d_in, const int* in_sizes, int n_in,
                              void* d_out, int out_size)
{
    const float* ht   = (const float*)d_in[0];
    const float* hc   = (const float*)d_in[1];
    const float* w_t1 = (const float*)d_in[2];
    const float* b_t1 = (const float*)d_in[3];
    const float* w_t2 = (const float*)d_in[4];
    const float* b_t2 = (const float*)d_in[5];
    const float* w_i1 = (const float*)d_in[6];
    const float* b_i1 = (const float*)d_in[7];
    const float* w_i2 = (const float*)d_in[8];
    const float* b_i2 = (const float*)d_in[9];
    float* out = (float*)d_out;

    __half *proj, *At16, *Ac16, *H1hi, *Bw1h, *Bi1h, *Bw2hi;
    cudaGetSymbolAddress((void**)&proj, g_proj);
    cudaGetSymbolAddress((void**)&At16, g_At16);
    cudaGetSymbolAddress((void**)&Ac16, g_Ac16);
    cudaGetSymbolAddress((void**)&H1hi, g_H1hi);
    cudaGetSymbolAddress((void**)&Bw1h, g_Bw1h);
    cudaGetSymbolAddress((void**)&Bi1h, g_Bi1h);
    cudaGetSymbolAddress((void**)&Bw2hi, g_Bw2hi);

    cudaFuncSetAttribute(mega_gemm, cudaFuncAttributeMaxDynamicSharedMemorySize, 196608);

    // unified prep (all fp16)
    prep_k<<<SPGRID + TW1GRID + TW2GRID, 256>>>(
        ht, hc, At16, Ac16, w_t1, w_i1, Bw1h, Bi1h, w_t2, Bw2hi);
    // mega GEMM: gemm1 + projections + vocab (2-stage 96KB, K=128 chunks)
    mega_gemm<<<G1GRID + PRGRID + VOGRID, 256, 196608>>>(
        At16, Bw1h, b_t1, H1hi,
        Ac16, Bi1h, b_i1, proj,
        Bw2hi, b_t2, out);
    // IoU combine + mask
    iou_mask_k<<<BB * TT * (TT + 1), 192>>>(proj, w_i2, b_i2, out);
}